// round 3
// baseline (speedup 1.0000x reference)
#include <cuda_runtime.h>
#include <cuda_bf16.h>

#define TT 256
#define NMAX 8192
#define SIGMA_INV (1.0f / 100.0f)
#define BLOCKS 512
#define THREADS 256
#define WPB 8                 // warps per block

// Scratch: device globals (allocation-free rule). Zero at module load; the
// LAST block re-zeros after consuming, so every graph replay sees clean state.
__device__ float        gS[TT];     // S[t] = sum_j ev_j [y_j > t] exp(F1[j,t]/s)
__device__ float        gE[NMAX];   // ev_i * exp(-A_i / sigma)
__device__ double       gL1;
__device__ unsigned int gCount;

// exp(x) for |x| <= 0.009 : cubic Taylor, rel err < 3e-10
__device__ __forceinline__ float exp_small(float x) {
    return fmaf(x, fmaf(x, fmaf(x, 0.16666667f, 0.5f), 1.0f), 1.0f);
}

__global__ void __launch_bounds__(THREADS)
surv_fused(const float* __restrict__ yp,
           const void*  __restrict__ yv,
           const float* __restrict__ status,
           int N,
           float* __restrict__ out) {
    const int t    = threadIdx.x;
    const int lane = t & 31;
    const int w    = t >> 5;

    // ---- detect y element width (int64 LE: odd 32-bit words all zero) ----
    __shared__ int sor;
    if (t == 0) sor = 0;
    __syncthreads();
    {
        const int* y32 = (const int*)yv;
        int idx = 2 * t + 1;
        int v = (idx < N) ? y32[idx] : 0;
        unsigned b = __ballot_sync(0xffffffffu, v != 0);
        if (lane == 0 && b) atomicOr(&sor, 1);
    }
    __syncthreads();
    const bool is64 = (sor == 0);

    // ---- Phase A: warp-per-row, software-pipelined over the row stride ----
    const int gw = blockIdx.x * WPB + w;
    const int GW = gridDim.x * WPB;        // 4096 -> 2 rows per warp at N=8192

    float acc[8];
    #pragma unroll
    for (int k = 0; k < 8; k++) acc[k] = 0.0f;
    float accL1 = 0.0f;

    int j = gw;
    float4 a0, a1;
    if (j < N) {
        const float* row = yp + (size_t)j * TT + lane * 8;
        a0 = *(const float4*)(row);
        a1 = *(const float4*)(row + 4);
    }
    while (j < N) {
        const int jn = j + GW;
        float4 b0, b1;
        if (jn < N) {                       // prefetch next row
            const float* rown = yp + (size_t)jn * TT + lane * 8;
            b0 = *(const float4*)(rown);
            b1 = *(const float4*)(rown + 4);
        }

        float v[8] = {a0.x, a0.y, a0.z, a0.w, a1.x, a1.y, a1.z, a1.w};

        // local inclusive prefix of 8
        float s[8];
        s[0] = v[0];
        #pragma unroll
        for (int k = 1; k < 8; k++) s[k] = s[k - 1] + v[k];

        // warp exclusive scan of lane totals
        const float tot = s[7];
        float sc = tot;
        #pragma unroll
        for (int o = 1; o < 32; o <<= 1) {
            float n = __shfl_up_sync(0xffffffffu, sc, o);
            if (lane >= o) sc += n;
        }
        const float off = sc - tot;

        // row metadata (lane 0 loads, broadcast)
        int yj = 0; float st = 0.0f;
        if (lane == 0) {
            yj = is64 ? (int)((const long long*)yv)[j] : ((const int*)yv)[j];
            st = status[j];
        }
        yj = __shfl_sync(0xffffffffu, yj, 0);
        st = __shfl_sync(0xffffffffu, st, 0);

        // extract A = F1[j, yj], p = y_pred[j, yj]
        const int srcLane = yj >> 3, srcIdx = yj & 7;
        float fa = 0.0f, va = 0.0f;
        #pragma unroll
        for (int k = 0; k < 8; k++)
            if (k == srcIdx) { fa = off + s[k]; va = v[k]; }
        const float A = __shfl_sync(0xffffffffu, fa, srcLane);
        const float p = __shfl_sync(0xffffffffu, va, srcLane);

        const bool ev = (st > 0.5f);
        if (lane == 0) {
            accL1 += -(st * __logf(p)) - (1.0f - st) * __logf(1.0f - A);
            gE[j] = ev ? exp_small(-A * SIGMA_INV) : 0.0f;
        }
        if (ev) {                           // warp-uniform branch
            const int base = lane * 8;
            #pragma unroll
            for (int k = 0; k < 8; k++) {
                float e = exp_small((off + s[k]) * SIGMA_INV);
                if (base + k < yj) acc[k] += e;
            }
        }

        a0 = b0; a1 = b1; j = jn;
    }

    // block-level reduce: acc -> gS (1 float atomic per column per block),
    // accL1 -> gL1 (1 double atomic per block)
    __shared__ float  sRed[WPB][TT];
    __shared__ double sD[WPB];
    #pragma unroll
    for (int k = 0; k < 8; k++) sRed[w][lane * 8 + k] = acc[k];
    if (lane == 0) sD[w] = (double)accL1;
    __syncthreads();
    {
        float colSum = 0.0f;
        #pragma unroll
        for (int ww = 0; ww < WPB; ww++) colSum += sRed[ww][t];
        if (colSum != 0.0f) atomicAdd(&gS[t], colSum);
        if (t == 0) {
            double l1 = 0.0;
            #pragma unroll
            for (int ww = 0; ww < WPB; ww++) l1 += sD[ww];
            atomicAdd(&gL1, l1);
        }
    }

    // ---- arrival counter: last block does Phase B + reset ----
    __threadfence();
    __shared__ bool isLast;
    if (t == 0) {
        unsigned old = atomicAdd(&gCount, 1u);
        isLast = (old == (unsigned)(gridDim.x - 1));
    }
    __syncthreads();
    if (!isLast) return;

    // Phase B: L2 = sum_i gE[i] * gS[y_i]; stage gS in shared (L2-coherent read)
    __shared__ float sS[TT];
    sS[t] = __ldcg(&gS[t]);
    __syncthreads();

    float l2 = 0.0f;
    for (int i = t; i < N; i += THREADS) {
        float e = __ldcg(&gE[i]);
        if (e != 0.0f) {
            int yi = is64 ? (int)((const long long*)yv)[i] : ((const int*)yv)[i];
            l2 += e * sS[yi];
        }
    }
    double d = (double)l2;
    #pragma unroll
    for (int o = 16; o > 0; o >>= 1)
        d += __shfl_down_sync(0xffffffffu, d, o);
    if (lane == 0) sD[w] = d;
    __syncthreads();
    if (t == 0) {
        double tot = 0.0;
        #pragma unroll
        for (int ww = 0; ww < WPB; ww++) tot += sD[ww];
        out[0] = (float)(gL1 + tot);
    }

    // reset for next replay
    __syncthreads();
    gS[t] = 0.0f;
    if (t == 0) { gL1 = 0.0; gCount = 0u; }
}

extern "C" void kernel_launch(void* const* d_in, const int* in_sizes, int n_in,
                              void* d_out, int out_size) {
    const float* y_pred = (const float*)d_in[0];
    const void*  y      = d_in[1];
    const float* status = (const float*)d_in[2];
    const int N = in_sizes[2];   // status length = N independent of y width
    surv_fused<<<BLOCKS, THREADS>>>(y_pred, y, status, N, (float*)d_out);
}

// round 4
// speedup vs baseline: 1.7843x; 1.7843x over previous
#include <cuda_runtime.h>
#include <cuda_bf16.h>

#define TT 256
#define NMAX 8192
#define SIGMA_INV (1.0f / 100.0f)
#define BLOCKS 304            // 2 per SM (152 SMs) — measured-best grid
#define THREADS 256
#define WPB 8                 // warps per block

// Scratch: device globals (allocation-free rule). Zero at module load; the
// LAST block re-zeros after consuming, so every graph replay sees clean state.
__device__ float        gS[TT];   // S[t] = sum_j ev_j [y_j > t] exp(F1[j,t]/s)
__device__ float        gH[TT];   // H[t] = sum_{i: y_i = t} ev_i exp(-A_i/s)
__device__ double       gL1;
__device__ unsigned int gCount;

// exp(x) for |x| <= 0.009 : cubic Taylor, rel err < 3e-10
__device__ __forceinline__ float exp_small(float x) {
    return fmaf(x, fmaf(x, fmaf(x, 0.16666667f, 0.5f), 1.0f), 1.0f);
}

__global__ void __launch_bounds__(THREADS)
surv_fused(const float* __restrict__ yp,
           const void*  __restrict__ yv,
           const float* __restrict__ status,
           int N,
           float* __restrict__ out) {
    const int t    = threadIdx.x;
    const int lane = t & 31;
    const int w    = t >> 5;

    __shared__ float  sH[TT];
    __shared__ int    sor;
    if (t == 0) sor = 0;
    sH[t] = 0.0f;
    __syncthreads();

    // ---- detect y element width (int64 LE: odd 32-bit words all zero) ----
    {
        const int* y32 = (const int*)yv;
        int idx = 2 * t + 1;
        int v = (idx < N) ? y32[idx] : 0;
        unsigned b = __ballot_sync(0xffffffffu, v != 0);
        if (lane == 0 && b) atomicOr(&sor, 1);
    }
    __syncthreads();
    const bool is64 = (sor == 0);

    // ---- Phase A: warp-per-row, software-pipelined over the row stride ----
    const int gw = blockIdx.x * WPB + w;
    const int GW = gridDim.x * WPB;        // 2432 -> ~3.4 rows per warp

    float acc[8];
    #pragma unroll
    for (int k = 0; k < 8; k++) acc[k] = 0.0f;
    float accL1 = 0.0f;

    int j = gw;
    float4 a0, a1;
    if (j < N) {
        const float* row = yp + (size_t)j * TT + lane * 8;
        a0 = *(const float4*)(row);
        a1 = *(const float4*)(row + 4);
    }
    while (j < N) {
        const int jn = j + GW;
        float4 b0, b1;
        if (jn < N) {                       // prefetch next row
            const float* rown = yp + (size_t)jn * TT + lane * 8;
            b0 = *(const float4*)(rown);
            b1 = *(const float4*)(rown + 4);
        }

        float v[8] = {a0.x, a0.y, a0.z, a0.w, a1.x, a1.y, a1.z, a1.w};

        // local inclusive prefix of 8
        float s[8];
        s[0] = v[0];
        #pragma unroll
        for (int k = 1; k < 8; k++) s[k] = s[k - 1] + v[k];

        // warp exclusive scan of lane totals
        const float tot = s[7];
        float sc = tot;
        #pragma unroll
        for (int o = 1; o < 32; o <<= 1) {
            float n = __shfl_up_sync(0xffffffffu, sc, o);
            if (lane >= o) sc += n;
        }
        const float off = sc - tot;

        // row metadata (lane 0 loads, broadcast)
        int yj = 0; float st = 0.0f;
        if (lane == 0) {
            yj = is64 ? (int)((const long long*)yv)[j] : ((const int*)yv)[j];
            st = status[j];
        }
        yj = __shfl_sync(0xffffffffu, yj, 0);
        st = __shfl_sync(0xffffffffu, st, 0);

        // extract A = F1[j, yj], p = y_pred[j, yj]
        const int srcLane = yj >> 3, srcIdx = yj & 7;
        float fa = 0.0f, va = 0.0f;
        #pragma unroll
        for (int k = 0; k < 8; k++)
            if (k == srcIdx) { fa = off + s[k]; va = v[k]; }
        const float A = __shfl_sync(0xffffffffu, fa, srcLane);
        const float p = __shfl_sync(0xffffffffu, va, srcLane);

        const bool ev = (st > 0.5f);
        if (lane == 0) {
            accL1 += -(st * __logf(p)) - (1.0f - st) * __logf(1.0f - A);
            if (ev) atomicAdd(&sH[yj], exp_small(-A * SIGMA_INV));
        }
        if (ev) {                           // warp-uniform branch
            const int base = lane * 8;
            #pragma unroll
            for (int k = 0; k < 8; k++) {
                float e = exp_small((off + s[k]) * SIGMA_INV);
                if (base + k < yj) acc[k] += e;
            }
        }

        a0 = b0; a1 = b1; j = jn;
    }

    // block-level reduce: acc -> gS, sH -> gH (1 float atomic per column per
    // block each), accL1 -> gL1 (1 double atomic per block)
    __shared__ float  sRed[WPB][TT];
    __shared__ double sD[WPB];
    #pragma unroll
    for (int k = 0; k < 8; k++) sRed[w][lane * 8 + k] = acc[k];
    if (lane == 0) sD[w] = (double)accL1;
    __syncthreads();
    {
        float colSum = 0.0f;
        #pragma unroll
        for (int ww = 0; ww < WPB; ww++) colSum += sRed[ww][t];
        if (colSum != 0.0f) atomicAdd(&gS[t], colSum);
        float h = sH[t];
        if (h != 0.0f) atomicAdd(&gH[t], h);
        if (t == 0) {
            double l1 = 0.0;
            #pragma unroll
            for (int ww = 0; ww < WPB; ww++) l1 += sD[ww];
            atomicAdd(&gL1, l1);
        }
    }

    // ---- arrival counter: last block finalizes + resets ----
    __threadfence();
    __shared__ bool isLast;
    if (t == 0) {
        unsigned old = atomicAdd(&gCount, 1u);
        isLast = (old == (unsigned)(gridDim.x - 1));
    }
    __syncthreads();
    if (!isLast) return;

    // Finalize: L2 = sum_t gS[t] * gH[t]  (256-element dot product)
    double d = (double)(__ldcg(&gS[t]) * __ldcg(&gH[t]));
    #pragma unroll
    for (int o = 16; o > 0; o >>= 1)
        d += __shfl_down_sync(0xffffffffu, d, o);
    if (lane == 0) sD[w] = d;
    __syncthreads();
    if (t == 0) {
        double tot = 0.0;
        #pragma unroll
        for (int ww = 0; ww < WPB; ww++) tot += sD[ww];
        out[0] = (float)(gL1 + tot);
    }

    // reset for next graph replay
    __syncthreads();
    gS[t] = 0.0f;
    gH[t] = 0.0f;
    if (t == 0) { gL1 = 0.0; gCount = 0u; }
}

extern "C" void kernel_launch(void* const* d_in, const int* in_sizes, int n_in,
                              void* d_out, int out_size) {
    const float* y_pred = (const float*)d_in[0];
    const void*  y      = d_in[1];
    const float* status = (const float*)d_in[2];
    const int N = in_sizes[2];   // status length = N independent of y width
    surv_fused<<<BLOCKS, THREADS>>>(y_pred, y, status, N, (float*)d_out);
}